// round 17
// baseline (speedup 1.0000x reference)
#include <cuda_runtime.h>
#include <cuda_fp16.h>
#include <math.h>
#include <stdint.h>

#define DIM  1024
#define NEXP 8
#define NTOK 16384
#define BM   128
#define BN   256
#define BK   64
#define KIT  (DIM/BK)        // 16 stages
#define ROWB 144             // fp16 row: 64 halves (128B) + 16B pad
#define ROW32 272            // fp32 row: 64 floats (256B) + 16B pad
#define GAP_THRESH 5.0e-3f
#define NROW (NTOK/BM)       // 128 row-blocks

// MODE 0 (gating): A fp32 staging | B fp16
#define M0_OFF_A 0
#define M0_OFF_B (128*ROW32)            // 34816
#define M0_STGB  (M0_OFF_B + 256*ROWB)  // 71680
#define M0_SMEM  (3*M0_STGB)            // 215040
// MODE 1 (expert): A fp16 | B fp16
#define M1_OFF_A 0
#define M1_OFF_B (128*ROWB)             // 18432
#define M1_STGB  (M1_OFF_B + 256*ROWB)  // 55296
#define M1_SMEM  (3*M1_STGB)            // 165888

// ---------------- device-global scratch (allocation-free) ----------------
__device__ __half g_Xh[(size_t)NTOK * DIM];
__device__ __half g_Wh[(size_t)(1 + NEXP) * DIM * DIM];   // [N][K] fp16
__device__ float  g_part[(size_t)NTOK * 32];
__device__ int    g_cnt[NEXP];
__device__ int    g_done[NROW];
__device__ int    g_tok[NEXP * NTOK];
__device__ float  g_p[NTOK];

// ---------------- PTX helpers ----------------
static __device__ __forceinline__ uint32_t smem_u32(const void* p) {
    uint32_t a;
    asm("{ .reg .u64 t; cvta.to.shared.u64 t, %1; cvt.u32.u64 %0, t; }" : "=r"(a) : "l"(p));
    return a;
}
#define CP_ASYNC16(dst, src, sz) \
    asm volatile("cp.async.cg.shared.global [%0], [%1], 16, %2;" \
                 :: "r"(dst), "l"(src), "r"(sz) : "memory")
#define CP_COMMIT() asm volatile("cp.async.commit_group;" ::: "memory")
#define CP_WAIT_1() asm volatile("cp.async.wait_group 1;" ::: "memory")

#define LDM_X4(r, addr) \
    asm volatile("ldmatrix.sync.aligned.m8n8.x4.shared.b16 {%0,%1,%2,%3}, [%4];" \
                 : "=r"((r)[0]), "=r"((r)[1]), "=r"((r)[2]), "=r"((r)[3]) : "r"(addr))

#define MMA(d, a, b0_, b1_) \
    asm volatile("mma.sync.aligned.m16n8k16.row.col.f32.f16.f16.f32 " \
                 "{%0,%1,%2,%3},{%4,%5,%6,%7},{%8,%9},{%0,%1,%2,%3};" \
                 : "+f"((d)[0]), "+f"((d)[1]), "+f"((d)[2]), "+f"((d)[3]) \
                 : "r"((a)[0]), "r"((a)[1]), "r"((a)[2]), "r"((a)[3]), \
                   "r"(b0_), "r"(b1_))

// pack two fp32 -> fp16x2 with round-to-nearest (identical to __float2half_rn)
static __device__ __forceinline__ uint32_t f2h2(float lo, float hi) {
    uint32_t r;
    asm("cvt.rn.f16x2.f32 %0, %1, %2;" : "=r"(r) : "f"(hi), "f"(lo));
    return r;
}

// ---- top-2 merge (first-index tie-break, jnp.argmax compatible) ----
static __device__ __forceinline__ void merge_top2(float& m1, int& i1, float& m2, int& i2,
                                                  float om1, int oi1, float om2, int oi2) {
    if (om1 > m1 || (om1 == m1 && oi1 < i1)) {
        float c = m1; int ci = i1;
        m1 = om1; i1 = oi1;
        if (om2 > c || (om2 == c && oi2 < ci)) { m2 = om2; i2 = oi2; }
        else                                   { m2 = c;   i2 = ci;  }
    } else {
        if (om1 > m2 || (om1 == m2 && oi1 < i2)) { m2 = om1; i2 = oi1; }
    }
}
static __device__ __forceinline__ void merge5(float& m1, int& i1, float& m2, int& i2, float& s,
                                              float om1, int oi1, float om2, int oi2, float os) {
    const float M = fmaxf(m1, om1);
    s = s * expf(m1 - M) + os * expf(om1 - M);
    merge_top2(m1, i1, m2, i2, om1, oi1, om2, oi2);
}

// =====================================================================
// Prep: Wg transpose -> g_Wh[z=0] (1024 blocks) + counter reset.
// =====================================================================
__global__ __launch_bounds__(256) void k_prep(const float* __restrict__ Wg) {
    const int id = blockIdx.x;
    const int tid = threadIdx.x;
    if (id == 0) {
        if (tid < NEXP) g_cnt[tid] = 0;
        if (tid < NROW) g_done[tid] = 0;
    }
    __shared__ float t[32][33];
    const int bx = id & 31, by = id >> 5;
    const int tx = tid & 31, ty = tid >> 5;
    #pragma unroll
    for (int i = 0; i < 32; i += 8)
        t[ty + i][tx] = Wg[(size_t)(by * 32 + ty + i) * DIM + bx * 32 + tx];
    __syncthreads();
    #pragma unroll
    for (int i = 0; i < 32; i += 8)
        g_Wh[(size_t)(bx * 32 + ty + i) * DIM + by * 32 + tx] =
            __float2half_rn(t[tx][ty + i]);
}

// =====================================================================
// fp16 GEMM via mma.sync (fp32 acc), BK=64, 3-stage cp.async pipeline.
// 512 threads = 16 warps as 4(m) x 4(n); warp tile 32x64; block 128x256.
// MODE 0: gating; grid (4, 128+32+128):
//   y <  128        : GEMM tile (A from fp32 X, frag via LDS+cvt) -> partials;
//                     last CTA of each row merges + rescues + routes.
//   y in [128,160)  : We transpose CTAs.
//   y >= 160        : X -> g_Xh conversion CTAs (for expert GEMM).
// MODE 1: expert -> out = relu(x@We[e] + be[e]) * p   (rows gathered via g_Xh)
// =====================================================================
template <int MODE>
__global__ __launch_bounds__(512, 1) void k_gemm(const float* __restrict__ bias_,
                                                 float* __restrict__ C,
                                                 const float* __restrict__ X32,
                                                 const float* __restrict__ Wg32,
                                                 const float* __restrict__ We32) {
    extern __shared__ char smem[];
    __shared__ int stok[BM];

    const int tid = threadIdx.x;
    const int lane = tid & 31;
    const int w = tid >> 5;

    constexpr int OFF_B = (MODE == 0) ? M0_OFF_B : M1_OFF_B;
    constexpr int STGB  = (MODE == 0) ? M0_STGB  : M1_STGB;

    // ================= aux CTAs (MODE 0, y >= 128) ================
    if (MODE == 0 && blockIdx.y >= NROW) {
        if (blockIdx.y >= NROW + 32) {
            // ---- X -> g_Xh conversion (grid-stride) ----
            const int idx = (blockIdx.y - (NROW + 32)) * 4 + blockIdx.x;  // 0..511
            const size_t total = (size_t)NTOK * DIM / 4;
            for (size_t i = (size_t)idx * 512 + tid; i < total; i += 512 * 512) {
                float4 v = ((const float4*)X32)[i];
                ((uint32_t*)g_Xh)[2 * i]     = f2h2(v.x, v.y);
                ((uint32_t*)g_Xh)[2 * i + 1] = f2h2(v.z, v.w);
            }
            return;
        }
        // ---- We transpose tile ----
        const int c_ = (blockIdx.y - NROW) * 4 + blockIdx.x;   // 0..127
        const int e = c_ >> 4;
        const int c0 = (c_ & 15) * 64;
        const float* src = We32 + (size_t)e * DIM * DIM;       // [K][N]
        __half* dst = g_Wh + (size_t)(1 + e) * DIM * DIM;      // [N][K]
        float* sbuf = (float*)smem;             // [64][65]
        const int rowt = tid >> 3;
        const int colt = (tid & 7) * 8;
        for (int r0 = 0; r0 < DIM; r0 += 64) {
            float4 v0 = *(const float4*)&src[(size_t)(r0 + rowt) * DIM + c0 + colt];
            float4 v1 = *(const float4*)&src[(size_t)(r0 + rowt) * DIM + c0 + colt + 4];
            __syncthreads();
            float* dr = &sbuf[rowt * 65 + colt];
            dr[0] = v0.x; dr[1] = v0.y; dr[2] = v0.z; dr[3] = v0.w;
            dr[4] = v1.x; dr[5] = v1.y; dr[6] = v1.z; dr[7] = v1.w;
            __syncthreads();
            __half tmp[8];
            #pragma unroll
            for (int j = 0; j < 8; ++j)
                tmp[j] = __float2half_rn(sbuf[(colt + j) * 65 + rowt]);
            *(uint4*)&dst[(size_t)(c0 + rowt) * DIM + r0 + colt] = *(uint4*)tmp;
        }
        return;
    }

    const int mbase = blockIdx.y * BM;
    const int nbase = blockIdx.x * BN;

    const float* bias = bias_;
    size_t woff = 0;
    if (MODE == 1) {
        const int e = blockIdx.z;
        const int cnt = g_cnt[e];
        if (mbase >= cnt) return;
        woff = (size_t)(1 + e) * DIM * DIM;
        bias = bias_ + e * DIM;
        if (tid < BM) {
            const int i = mbase + tid;
            stok[tid] = (i < cnt) ? g_tok[e * NTOK + i] : -1;
        }
        __syncthreads();
    }

    const uint32_t sb = smem_u32(smem);

    // ---- A-load setup ----
    const char* gA0 = nullptr; const char* gA1 = nullptr;   // MODE 1
    uint32_t szA0 = 16u, szA1 = 16u, soA0 = 0, soA1 = 0;
    const char* gA32 = nullptr; uint32_t soA32 = 0;         // MODE 0
    if (MODE == 0) {
        const int a_r = tid >> 2;               // row 0..127
        const int cb = (tid & 3) * 64;          // 4 x 16B chunks per thread
        gA32 = (const char*)(X32 + (size_t)(mbase + a_r) * DIM) + cb;
        soA32 = M0_OFF_A + a_r * ROW32 + cb;
    } else {
        const int c8 = (tid & 7) * 16;
        const int r0_ = tid >> 3;
        const int tokA0 = stok[r0_];
        const int tokA1 = stok[r0_ + 64];
        gA0 = (const char*)(g_Xh + (size_t)(tokA0 >= 0 ? tokA0 : 0) * DIM) + c8;
        gA1 = (const char*)(g_Xh + (size_t)(tokA1 >= 0 ? tokA1 : 0) * DIM) + c8;
        szA0 = (tokA0 >= 0) ? 16u : 0u;
        szA1 = (tokA1 >= 0) ? 16u : 0u;
        soA0 = M1_OFF_A + r0_ * ROWB + c8;
        soA1 = soA0 + 64 * ROWB;
    }
    // ---- B-load setup (same both modes) ----
    const int c8b = (tid & 7) * 16;
    const int rb = tid >> 3;
    const char* gB = (const char*)(g_Wh + woff + (size_t)(nbase + rb) * DIM) + c8b;
    const uint32_t soB = OFF_B + rb * ROWB + c8b;

    const int wm = (w & 3) * 32;
    const int wn = (w >> 2) * 64;
    const int lr = lane & 15;
    const int lkb = (lane >> 4) * 16;
    const int arow = (lane >> 2);       // fragment row within 8
    const int acol = (lane & 3) * 2;    // fragment col pair

    float acc[2][8][4];
    #pragma unroll
    for (int mi = 0; mi < 2; ++mi)
        #pragma unroll
        for (int nj = 0; nj < 8; ++nj)
            #pragma unroll
            for (int q = 0; q < 4; ++q) acc[mi][nj][q] = 0.f;

    // prologue: stages 0, 1
    #pragma unroll
    for (int s = 0; s < 2; ++s) {
        const uint32_t d = sb + s * STGB;
        if (MODE == 0) {
            const int ko = s * (BK * 4);   // fp32: 256B per stage
            #pragma unroll
            for (int q = 0; q < 4; ++q)
                CP_ASYNC16(d + soA32 + q * 16, gA32 + ko + q * 16, 16u);
        } else {
            const int ko = s * (BK * 2);
            CP_ASYNC16(d + soA0, gA0 + ko, szA0);
            CP_ASYNC16(d + soA1, gA1 + ko, szA1);
        }
        const int kob = s * (BK * 2);
        #pragma unroll
        for (int tb = 0; tb < 4; ++tb)
            CP_ASYNC16(d + soB + tb * (64 * ROWB), gB + tb * (64 * DIM * 2) + kob, 16u);
        CP_COMMIT();
    }

    int rd = 0, wr = 2;
    for (int it = 0; it < KIT; ++it) {
        CP_WAIT_1();
        __syncthreads();

        if (it + 2 < KIT) {
            const uint32_t d = sb + wr * STGB;
            if (MODE == 0) {
                const int ko = (it + 2) * (BK * 4);
                #pragma unroll
                for (int q = 0; q < 4; ++q)
                    CP_ASYNC16(d + soA32 + q * 16, gA32 + ko + q * 16, 16u);
            } else {
                const int ko = (it + 2) * (BK * 2);
                CP_ASYNC16(d + soA0, gA0 + ko, szA0);
                CP_ASYNC16(d + soA1, gA1 + ko, szA1);
            }
            const int kob = (it + 2) * (BK * 2);
            #pragma unroll
            for (int tb = 0; tb < 4; ++tb)
                CP_ASYNC16(d + soB + tb * (64 * ROWB), gB + tb * (64 * DIM * 2) + kob, 16u);
        }
        CP_COMMIT();

        const uint32_t sgb = sb + rd * STGB;
        const char* sgc = smem + rd * STGB;
        #pragma unroll
        for (int kk = 0; kk < 4; ++kk) {
            uint32_t ah[2][4];
            if (MODE == 0) {
                // build A fragments from fp32 staging (bit-identical cvt.rn)
                #pragma unroll
                for (int mi = 0; mi < 2; ++mi) {
                    #pragma unroll
                    for (int j = 0; j < 4; ++j) {
                        const int row = wm + mi * 16 + arow + (j & 1) * 8;
                        const int col = kk * 16 + acol + (j >> 1) * 8;
                        const float2 v = *(const float2*)(sgc + M0_OFF_A + row * ROW32 + col * 4);
                        ah[mi][j] = f2h2(v.x, v.y);
                    }
                }
            } else {
                const uint32_t kb = kk * 32 + lkb;
                #pragma unroll
                for (int mi = 0; mi < 2; ++mi) {
                    const uint32_t ro = (uint32_t)(wm + mi * 16 + lr) * ROWB + kb;
                    LDM_X4(ah[mi], sgb + M1_OFF_A + ro);
                }
            }
            const uint32_t kb = kk * 32 + lkb;
            #pragma unroll
            for (int njp = 0; njp < 4; ++njp) {
                uint32_t bh[4];
                const uint32_t ro = (uint32_t)(wn + njp * 16 + lr) * ROWB + kb;
                LDM_X4(bh, sgb + OFF_B + ro);
                #pragma unroll
                for (int mi = 0; mi < 2; ++mi)
                    #pragma unroll
                    for (int t = 0; t < 2; ++t)
                        MMA(acc[mi][njp * 2 + t], ah[mi], bh[t], bh[t + 2]);
            }
        }
        rd = (rd == 2) ? 0 : rd + 1;
        wr = (wr == 2) ? 0 : wr + 1;
    }

    const int gid = lane >> 2;
    const int tq = lane & 3;

    if (MODE == 1) {
        #pragma unroll
        for (int mi = 0; mi < 2; ++mi) {
            #pragma unroll
            for (int rh = 0; rh < 2; ++rh) {
                const int mloc = wm + mi * 16 + gid + rh * 8;
                const int tok = stok[mloc];
                if (tok < 0) continue;
                const float pt = g_p[tok];
                float* dst = C + (size_t)tok * DIM;
                #pragma unroll
                for (int nj = 0; nj < 8; ++nj) {
                    const int n = nbase + wn + nj * 8 + tq * 2;
                    float v0 = fmaxf(acc[mi][nj][rh * 2]     + bias[n], 0.f) * pt;
                    float v1 = fmaxf(acc[mi][nj][rh * 2 + 1] + bias[n + 1], 0.f) * pt;
                    *(float2*)(dst + n) = make_float2(v0, v1);
                }
            }
        }
        return;
    }

    // ================= gating epilogue: partials =================
    {
        float* st_m1 = (float*)(smem + STGB);   // slot 1 (idle by now)
        float* st_m2 = st_m1 + 512;
        float* st_s  = st_m1 + 1024;
        int*   st_i1 = (int*)(st_m1 + 1536);
        int*   st_i2 = (int*)(st_m1 + 2048);
        const int wnidx = w >> 2;

        #pragma unroll
        for (int mi = 0; mi < 2; ++mi) {
            #pragma unroll
            for (int rh = 0; rh < 2; ++rh) {
                const int row = wm + mi * 16 + gid + rh * 8;
                float m1 = -3.4e38f, m2 = -3.4e38f;
                int i1 = 0x7fffffff, i2 = 0x7fffffff;
                float vals[16];
                #pragma unroll
                for (int nj = 0; nj < 8; ++nj) {
                    #pragma unroll
                    for (int cc = 0; cc < 2; ++cc) {
                        const int n = nbase + wn + nj * 8 + tq * 2 + cc;
                        const float v = acc[mi][nj][rh * 2 + cc] + bias[n];
                        vals[nj * 2 + cc] = v;
                        if (v > m1) { m2 = m1; i2 = i1; m1 = v; i1 = n; }
                        else if (v > m2) { m2 = v; i2 = n; }
                    }
                }
                float s = 0.f;
                #pragma unroll
                for (int q = 0; q < 16; ++q) s += expf(vals[q] - m1);
                #pragma unroll
                for (int off = 1; off <= 2; off <<= 1) {
                    const float om1 = __shfl_xor_sync(0xffffffffu, m1, off);
                    const int   oi1 = __shfl_xor_sync(0xffffffffu, i1, off);
                    const float om2 = __shfl_xor_sync(0xffffffffu, m2, off);
                    const int   oi2 = __shfl_xor_sync(0xffffffffu, i2, off);
                    const float os  = __shfl_xor_sync(0xffffffffu, s,  off);
                    merge5(m1, i1, m2, i2, s, om1, oi1, om2, oi2, os);
                }
                if (tq == 0) {
                    const int idx = wnidx * 128 + row;
                    st_m1[idx] = m1; st_m2[idx] = m2; st_s[idx] = s;
                    st_i1[idx] = i1; st_i2[idx] = i2;
                }
            }
        }
        __syncthreads();
        if (tid < 128) {
            float m1 = st_m1[tid], m2 = st_m2[tid], s = st_s[tid];
            int i1 = st_i1[tid], i2 = st_i2[tid];
            #pragma unroll
            for (int x = 1; x < 4; ++x) {
                const int idx = x * 128 + tid;
                merge5(m1, i1, m2, i2, s,
                       st_m1[idx], st_i1[idx], st_m2[idx], st_i2[idx], st_s[idx]);
            }
            float* P = g_part + (size_t)(mbase + tid) * 32 + blockIdx.x * 8;
            P[0] = m1; P[1] = m2; P[2] = s;
            P[3] = __int_as_float(i1); P[4] = __int_as_float(i2);
        }
    }

    // ================= fused route: last CTA of this row-block =============
    __shared__ int s_last;
    __syncthreads();
    if (tid == 0) {
        __threadfence();
        const int v = atomicAdd(&g_done[blockIdx.y], 1);
        s_last = (v == 3);
    }
    __syncthreads();
    if (!s_last) return;

    __shared__ float r_m1[128], r_m2[128], r_sum[128];
    __shared__ int   r_i1[128], r_i2[128];
    __shared__ int   amb_list[128];
    __shared__ int   amb_cnt;
    if (tid == 0) amb_cnt = 0;
    __syncthreads();

    if (tid < 128) {
        const int t = mbase + tid;
        const float* P = g_part + (size_t)t * 32;
        float m1 = P[0], m2 = P[1], s = P[2];
        int i1 = __float_as_int(P[3]), i2 = __float_as_int(P[4]);
        #pragma unroll
        for (int x = 1; x < 4; ++x) {
            const float* Q = P + x * 8;
            merge5(m1, i1, m2, i2, s,
                   Q[0], __float_as_int(Q[3]), Q[1], __float_as_int(Q[4]), Q[2]);
        }
        r_m1[tid] = m1; r_m2[tid] = m2; r_sum[tid] = s;
        r_i1[tid] = i1; r_i2[tid] = i2;
        if ((m1 - m2) < GAP_THRESH) {
            const int p = atomicAdd(&amb_cnt, 1);
            amb_list[p] = tid;
        }
    }
    __syncthreads();

    for (int a = w; a < amb_cnt; a += 16) {
        const int li = amb_list[a];
        const int t = mbase + li;
        const int c1 = r_i1[li], c2 = r_i2[li];
        float p1 = 0.f, p2 = 0.f;
        const float* xr = X32 + (size_t)t * DIM;
        for (int k = lane; k < DIM; k += 32) {
            const float xv = xr[k];
            p1 += xv * Wg32[(size_t)k * DIM + c1];
            p2 += xv * Wg32[(size_t)k * DIM + c2];
        }
        #pragma unroll
        for (int off = 16; off > 0; off >>= 1) {
            p1 += __shfl_down_sync(0xffffffffu, p1, off);
            p2 += __shfl_down_sync(0xffffffffu, p2, off);
        }
        if (lane == 0) {
            const float d1 = bias[c1] + p1;
            const float d2 = bias[c2] + p2;
            if (d2 > d1 || (d2 == d1 && c2 < c1)) { r_i1[li] = c2; r_m1[li] = r_m2[li]; }
        }
    }
    __syncthreads();

    if (tid < 128) {
        const int t = mbase + tid;
        const int chosen = r_i1[tid];
        const int ex = chosen & (NEXP - 1);
        const int pos = atomicAdd(&g_cnt[ex], 1);
        g_tok[ex * NTOK + pos] = t;
        const float lmax = fmaxf(r_m1[tid], r_m2[tid]);
        g_p[t] = expf(r_m1[tid] - lmax) / r_sum[tid];
    }
}

// =====================================================================
extern "C" void kernel_launch(void* const* d_in, const int* in_sizes, int n_in,
                              void* d_out, int out_size) {
    const float* x  = (const float*)d_in[0];
    const float* Wg = (const float*)d_in[1];
    const float* bg = (const float*)d_in[2];
    const float* We = (const float*)d_in[3];
    const float* be = (const float*)d_in[4];
    float* out = (float*)d_out;

    cudaFuncSetAttribute(k_gemm<0>, cudaFuncAttributeMaxDynamicSharedMemorySize, M0_SMEM);
    cudaFuncSetAttribute(k_gemm<1>, cudaFuncAttributeMaxDynamicSharedMemorySize, M1_SMEM);

    k_prep<<<1024, 256>>>(Wg);
    k_gemm<0><<<dim3(DIM / BN, NROW + 32 + 128), 512, M0_SMEM>>>(bg, nullptr, x, Wg, We);
    k_gemm<1><<<dim3(DIM / BN, NROW, NEXP), 512, M1_SMEM>>>(be, out, x, Wg, We);
}